// round 10
// baseline (speedup 1.0000x reference)
#include <cuda_runtime.h>
#include <cuda_bf16.h>
#include <math.h>

#define MAX_NODES 50000
#define D 16
#define NTYPES 16

// Scratch (allocation-free rule: __device__ globals)
__device__ int   g_cnt_out[MAX_NODES * NTYPES]; // out-edge type counts
__device__ int   g_cnt_in [MAX_NODES * NTYPES]; // in-edge type counts
__device__ float g_cf[MAX_NODES * NTYPES];      // float net counts (out - in)
__device__ float g_xT[MAX_NODES * D];           // node-major normalized reps
__device__ int   g_pos[NTYPES];                 // bucket fill counters -> final counts
__device__ int   g_bucket[NTYPES * MAX_NODES];  // per-type node lists

// ---------------------------------------------------------------- K0: zero counters + out
__global__ void k_zero(float* out) {
    int i = blockIdx.x * blockDim.x + threadIdx.x;
    int total4 = (MAX_NODES * NTYPES) / 4;
    if (i < total4) {
        reinterpret_cast<int4*>(g_cnt_out)[i] = make_int4(0, 0, 0, 0);
        reinterpret_cast<int4*>(g_cnt_in )[i] = make_int4(0, 0, 0, 0);
    }
    if (i < NTYPES) g_pos[i] = 0;
    if (i == 0) out[0] = 0.0f;
}

// ---------------------------------------------------------------- K1: per-edge type counts (2 atomics/edge)
__global__ void __launch_bounds__(256)
k_count(const int* __restrict__ src, const int* __restrict__ dst,
        const int* __restrict__ types, int n_edges) {
    int e = blockIdx.x * blockDim.x + threadIdx.x;
    if (e >= n_edges) return;
    int s  = src[e];
    int d  = dst[e];
    int ts = __ldg(types + s);
    int td = __ldg(types + d);
    atomicAdd(&g_cnt_out[s * NTYPES + td], 1);
    atomicAdd(&g_cnt_in [d * NTYPES + ts], 1);
}

// ---------------------------------------------------------------- K2: fused bucket scatter + invdeg + transpose-normalize + float counts
__global__ void __launch_bounds__(256)
k_prep(const float* __restrict__ reps, const int* __restrict__ types, int n_nodes) {
    __shared__ float s_tile[D][257];   // pitch 257: conflict-free column reads
    __shared__ float s_inv[256];
    __shared__ int s_hist[NTYPES], s_base[NTYPES];

    int tid  = threadIdx.x;
    int base = blockIdx.x * 256;
    int v    = base + tid;

    if (tid < NTYPES) s_hist[tid] = 0;
    __syncthreads();

    int t = 0, lrank = 0;
    if (v < n_nodes) {
        t = __ldg(types + v);
        lrank = atomicAdd(&s_hist[t], 1);     // smem atomic
    }

    // coalesced tile load: 16 rows of 1KB
    #pragma unroll
    for (int i = 0; i < D; i++)
        s_tile[i][tid] = (v < n_nodes) ? __ldg(reps + i * n_nodes + v) : 0.0f;

    float inv = 0.0f;
    if (v < n_nodes) {
        const int4* co = reinterpret_cast<const int4*>(g_cnt_out + v * NTYPES);
        const int4* ci = reinterpret_cast<const int4*>(g_cnt_in  + v * NTYPES);
        int4 o0 = co[0], o1 = co[1], o2 = co[2], o3 = co[3];
        int4 i0 = ci[0], i1 = ci[1], i2 = ci[2], i3 = ci[3];
        // in-degree = sum of cnt_in row
        int deg = i0.x+i0.y+i0.z+i0.w + i1.x+i1.y+i1.z+i1.w
                + i2.x+i2.y+i2.z+i2.w + i3.x+i3.y+i3.z+i3.w;
        inv = (deg > 0) ? rsqrtf((float)deg) : 0.0f;
        // net counts as floats (each thread writes its node's contiguous 64B)
        float4* cf = reinterpret_cast<float4*>(g_cf + v * NTYPES);
        cf[0] = make_float4((float)(o0.x-i0.x), (float)(o0.y-i0.y), (float)(o0.z-i0.z), (float)(o0.w-i0.w));
        cf[1] = make_float4((float)(o1.x-i1.x), (float)(o1.y-i1.y), (float)(o1.z-i1.z), (float)(o1.w-i1.w));
        cf[2] = make_float4((float)(o2.x-i2.x), (float)(o2.y-i2.y), (float)(o2.z-i2.z), (float)(o2.w-i2.w));
        cf[3] = make_float4((float)(o3.x-i3.x), (float)(o3.y-i3.y), (float)(o3.z-i3.z), (float)(o3.w-i3.w));
    }
    s_inv[tid] = inv;
    __syncthreads();

    if (tid < NTYPES) s_base[tid] = atomicAdd(&g_pos[tid], s_hist[tid]);
    __syncthreads();

    if (v < n_nodes)
        g_bucket[t * MAX_NODES + s_base[t] + lrank] = v;

    // coalesced node-major write of normalized x
    int limit = n_nodes - base;
    #pragma unroll
    for (int k = 0; k < 16; k++) {
        int f = k * 256 + tid;
        int n = f >> 4, i = f & 15;
        if (n < limit)
            g_xT[base * D + f] = s_tile[i][n] * s_inv[n];
    }
}

// ---------------------------------------------------------------- K3: weighted matvec + sum of squares
// Block serves ONE type, 64 nodes, 4 threads/node (4 output rows each).
// R[type] staged in smem; all matrix reads warp-uniform broadcasts.
__global__ void __launch_bounds__(256)
k_node(const float* __restrict__ R, float* out) {
    int type  = blockIdx.y;
    int count = __ldg(&g_pos[type]);
    int base  = blockIdx.x * 64;
    if (base >= count) return;

    __shared__ float sR[NTYPES * D * D];      // 16 KB: R[type][t][i][j]
    {
        const float4* Rg = reinterpret_cast<const float4*>(R) + (type << 10);
        float4* s4 = reinterpret_cast<float4*>(sR);
        #pragma unroll
        for (int k = 0; k < 4; k++)
            s4[threadIdx.x + k * 256] = Rg[threadIdx.x + k * 256];
    }
    __syncthreads();

    int node_local = threadIdx.x >> 2;        // 0..63
    int rg         = threadIdx.x & 3;         // row group: rows rg*4 .. rg*4+3
    int idx = base + node_local;

    float acc = 0.0f;
    if (idx < count) {
        int v = g_bucket[type * MAX_NODES + idx];
        const float4* xg = reinterpret_cast<const float4*>(g_xT + v * D);
        float4 x0 = xg[0], x1 = xg[1], x2 = xg[2], x3 = xg[3];
        const float4* cg = reinterpret_cast<const float4*>(g_cf + v * NTYPES);
        float4 c0 = cg[0], c1 = cg[1], c2 = cg[2], c3 = cg[3];
        float cf[NTYPES] = { c0.x,c0.y,c0.z,c0.w, c1.x,c1.y,c1.z,c1.w,
                             c2.x,c2.y,c2.z,c2.w, c3.x,c3.y,c3.z,c3.w };

        #pragma unroll 1
        for (int r = 0; r < 4; r++) {         // outer loop NOT unrolled (I$)
            int i = rg * 4 + r;
            float y = 0.0f;
            #pragma unroll
            for (int t = 0; t < NTYPES; t++) {
                const float4* row = reinterpret_cast<const float4*>(sR + t * 256 + i * 16);
                float4 r0 = row[0], r1 = row[1], r2 = row[2], r3 = row[3];
                float dotv = r0.x*x0.x + r0.y*x0.y + r0.z*x0.z + r0.w*x0.w
                           + r1.x*x1.x + r1.y*x1.y + r1.z*x1.z + r1.w*x1.w
                           + r2.x*x2.x + r2.y*x2.y + r2.z*x2.z + r2.w*x2.w
                           + r3.x*x3.x + r3.y*x3.y + r3.z*x3.z + r3.w*x3.w;
                y = fmaf(cf[t], dotv, y);
            }
            acc = fmaf(y, y, acc);
        }
    }

    // block reduce -> one atomicAdd per block
    #pragma unroll
    for (int off = 16; off > 0; off >>= 1)
        acc += __shfl_down_sync(0xFFFFFFFFu, acc, off);
    __shared__ float warp_sums[8];
    int lane = threadIdx.x & 31;
    int wid  = threadIdx.x >> 5;
    if (lane == 0) warp_sums[wid] = acc;
    __syncthreads();
    if (wid == 0) {
        float s = (lane < 8) ? warp_sums[lane] : 0.0f;
        #pragma unroll
        for (int off = 4; off > 0; off >>= 1)
            s += __shfl_down_sync(0xFFu, s, off);
        if (lane == 0) atomicAdd(out, s);
    }
}

// ---------------------------------------------------------------- launch
extern "C" void kernel_launch(void* const* d_in, const int* in_sizes, int n_in,
                              void* d_out, int out_size) {
    const float* reps  = (const float*)d_in[0];  // [16, n_nodes]
    const float* rmaps = (const float*)d_in[1];  // [16,16,16,16]
    const int*   eidx  = (const int*)d_in[2];    // [2, n_edges]
    const int*   types = (const int*)d_in[3];    // [n_nodes]
    float* out = (float*)d_out;

    int n_nodes = in_sizes[3];
    if (n_nodes > MAX_NODES) n_nodes = MAX_NODES;
    int n_edges = in_sizes[2] / 2;
    const int* src = eidx;
    const int* dst = eidx + n_edges;

    const int T = 256;

    k_zero <<<(MAX_NODES * NTYPES / 4 + T - 1) / T, T>>>(out);
    k_count<<<(n_edges + T - 1) / T, T>>>(src, dst, types, n_edges);
    k_prep <<<(n_nodes + T - 1) / T, T>>>(reps, types, n_nodes);

    dim3 grid((n_nodes + 63) / 64, NTYPES);   // non-working blocks exit early
    k_node <<<grid, 256>>>(rmaps, out);
}

// round 11
// speedup vs baseline: 2.5959x; 2.5959x over previous
#include <cuda_runtime.h>
#include <cuda_bf16.h>
#include <math.h>

#define MAX_NODES 50000
#define D 16
#define NTYPES 16
#define RPB 4   // rows per k_node block (grid.z = D/RPB)

// Scratch (allocation-free rule: __device__ globals)
__device__ int   g_cnt_out[MAX_NODES * NTYPES]; // out-edge type counts
__device__ int   g_cnt_in [MAX_NODES * NTYPES]; // in-edge type counts
__device__ float g_cf[MAX_NODES * NTYPES];      // float net counts (out - in)
__device__ float g_xT[MAX_NODES * D];           // node-major normalized reps
__device__ int   g_pos[NTYPES];                 // bucket fill counters -> final counts
__device__ int   g_bucket[NTYPES * MAX_NODES];  // per-type node lists

// ---------------------------------------------------------------- K0: zero counters + out
__global__ void k_zero(float* out) {
    int i = blockIdx.x * blockDim.x + threadIdx.x;
    int total4 = (MAX_NODES * NTYPES) / 4;
    if (i < total4) {
        reinterpret_cast<int4*>(g_cnt_out)[i] = make_int4(0, 0, 0, 0);
        reinterpret_cast<int4*>(g_cnt_in )[i] = make_int4(0, 0, 0, 0);
    }
    if (i < NTYPES) g_pos[i] = 0;
    if (i == 0) out[0] = 0.0f;
}

// ---------------------------------------------------------------- K1: per-edge type counts (2 atomics/edge)
__global__ void __launch_bounds__(256)
k_count(const int* __restrict__ src, const int* __restrict__ dst,
        const int* __restrict__ types, int n_edges) {
    int e = blockIdx.x * blockDim.x + threadIdx.x;
    if (e >= n_edges) return;
    int s  = src[e];
    int d  = dst[e];
    int ts = __ldg(types + s);
    int td = __ldg(types + d);
    atomicAdd(&g_cnt_out[s * NTYPES + td], 1);
    atomicAdd(&g_cnt_in [d * NTYPES + ts], 1);
}

// ---------------------------------------------------------------- K2: fused bucket scatter + invdeg + transpose-normalize + float counts
__global__ void __launch_bounds__(256)
k_prep(const float* __restrict__ reps, const int* __restrict__ types, int n_nodes) {
    __shared__ float s_tile[D][257];   // pitch 257: conflict-free column reads
    __shared__ float s_inv[256];
    __shared__ int s_hist[NTYPES], s_base[NTYPES];

    int tid  = threadIdx.x;
    int base = blockIdx.x * 256;
    int v    = base + tid;

    if (tid < NTYPES) s_hist[tid] = 0;
    __syncthreads();

    int t = 0, lrank = 0;
    if (v < n_nodes) {
        t = __ldg(types + v);
        lrank = atomicAdd(&s_hist[t], 1);     // smem atomic
    }

    // coalesced tile load: 16 rows of 1KB
    #pragma unroll
    for (int i = 0; i < D; i++)
        s_tile[i][tid] = (v < n_nodes) ? __ldg(reps + i * n_nodes + v) : 0.0f;

    float inv = 0.0f;
    if (v < n_nodes) {
        const int4* co = reinterpret_cast<const int4*>(g_cnt_out + v * NTYPES);
        const int4* ci = reinterpret_cast<const int4*>(g_cnt_in  + v * NTYPES);
        int4 o0 = co[0], o1 = co[1], o2 = co[2], o3 = co[3];
        int4 i0 = ci[0], i1 = ci[1], i2 = ci[2], i3 = ci[3];
        int deg = i0.x+i0.y+i0.z+i0.w + i1.x+i1.y+i1.z+i1.w
                + i2.x+i2.y+i2.z+i2.w + i3.x+i3.y+i3.z+i3.w;
        inv = (deg > 0) ? rsqrtf((float)deg) : 0.0f;
        float4* cf = reinterpret_cast<float4*>(g_cf + v * NTYPES);
        cf[0] = make_float4((float)(o0.x-i0.x), (float)(o0.y-i0.y), (float)(o0.z-i0.z), (float)(o0.w-i0.w));
        cf[1] = make_float4((float)(o1.x-i1.x), (float)(o1.y-i1.y), (float)(o1.z-i1.z), (float)(o1.w-i1.w));
        cf[2] = make_float4((float)(o2.x-i2.x), (float)(o2.y-i2.y), (float)(o2.z-i2.z), (float)(o2.w-i2.w));
        cf[3] = make_float4((float)(o3.x-i3.x), (float)(o3.y-i3.y), (float)(o3.z-i3.z), (float)(o3.w-i3.w));
    }
    s_inv[tid] = inv;
    __syncthreads();

    if (tid < NTYPES) s_base[tid] = atomicAdd(&g_pos[tid], s_hist[tid]);
    __syncthreads();

    if (v < n_nodes)
        g_bucket[t * MAX_NODES + s_base[t] + lrank] = v;

    // coalesced node-major write of normalized x
    int limit = n_nodes - base;
    #pragma unroll
    for (int k = 0; k < 16; k++) {
        int f = k * 256 + tid;
        int n = f >> 4, i = f & 15;
        if (n < limit)
            g_xT[base * D + f] = s_tile[i][n] * s_inv[n];
    }
}

// ---------------------------------------------------------------- K3: weighted matvec + sum of squares
// Block serves ONE (type, row-slice): thread = node (warp-uniform LDS), block
// handles RPB=4 output rows; grid.z spans the 16 rows. 4x warp parallelism
// vs R9 without breaking smem broadcast (R10's intra-warp row split caused
// 4-way bank conflicts: row stride 64 floats == bank-aligned).
__global__ void __launch_bounds__(256)
k_node(const float* __restrict__ R, float* out) {
    int type  = blockIdx.y;
    int count = __ldg(&g_pos[type]);
    int base  = blockIdx.x * 256;
    if (base >= count) return;
    int ro = blockIdx.z * RPB;                 // first row of this block's slice

    // sR[t][r][j] : rows ro..ro+3 of every R[type][t]  (4 KB)
    __shared__ float sR[NTYPES * RPB * 16];
    {
        int w = threadIdx.x;                   // 256 float4 entries
        int t = w >> 4, r = (w >> 2) & 3, j4 = w & 3;
        const float4* src = reinterpret_cast<const float4*>(R)
                          + (type << 10) + (t << 6) + ((ro + r) << 2) + j4;
        reinterpret_cast<float4*>(sR)[w] = *src;
    }
    __syncthreads();

    int idx = base + threadIdx.x;
    float acc = 0.0f;
    if (idx < count) {
        int v = g_bucket[type * MAX_NODES + idx];
        const float4* xg = reinterpret_cast<const float4*>(g_xT + v * D);
        float4 x0 = xg[0], x1 = xg[1], x2 = xg[2], x3 = xg[3];
        const float4* cg = reinterpret_cast<const float4*>(g_cf + v * NTYPES);
        float4 c0 = cg[0], c1 = cg[1], c2 = cg[2], c3 = cg[3];
        float cf[NTYPES] = { c0.x,c0.y,c0.z,c0.w, c1.x,c1.y,c1.z,c1.w,
                             c2.x,c2.y,c2.z,c2.w, c3.x,c3.y,c3.z,c3.w };

        #pragma unroll 1
        for (int r = 0; r < RPB; r++) {        // outer loop NOT unrolled (I$)
            float y = 0.0f;
            #pragma unroll
            for (int t = 0; t < NTYPES; t++) {
                const float4* row = reinterpret_cast<const float4*>(sR + t * (RPB*16) + r * 16);
                float4 r0 = row[0], r1 = row[1], r2 = row[2], r3 = row[3];
                float dotv = r0.x*x0.x + r0.y*x0.y + r0.z*x0.z + r0.w*x0.w
                           + r1.x*x1.x + r1.y*x1.y + r1.z*x1.z + r1.w*x1.w
                           + r2.x*x2.x + r2.y*x2.y + r2.z*x2.z + r2.w*x2.w
                           + r3.x*x3.x + r3.y*x3.y + r3.z*x3.z + r3.w*x3.w;
                y = fmaf(cf[t], dotv, y);
            }
            acc = fmaf(y, y, acc);
        }
    }

    // block reduce -> one atomicAdd per block
    #pragma unroll
    for (int off = 16; off > 0; off >>= 1)
        acc += __shfl_down_sync(0xFFFFFFFFu, acc, off);
    __shared__ float warp_sums[8];
    int lane = threadIdx.x & 31;
    int wid  = threadIdx.x >> 5;
    if (lane == 0) warp_sums[wid] = acc;
    __syncthreads();
    if (wid == 0) {
        float s = (lane < 8) ? warp_sums[lane] : 0.0f;
        #pragma unroll
        for (int off = 4; off > 0; off >>= 1)
            s += __shfl_down_sync(0xFFu, s, off);
        if (lane == 0) atomicAdd(out, s);
    }
}

// ---------------------------------------------------------------- launch
extern "C" void kernel_launch(void* const* d_in, const int* in_sizes, int n_in,
                              void* d_out, int out_size) {
    const float* reps  = (const float*)d_in[0];  // [16, n_nodes]
    const float* rmaps = (const float*)d_in[1];  // [16,16,16,16]
    const int*   eidx  = (const int*)d_in[2];    // [2, n_edges]
    const int*   types = (const int*)d_in[3];    // [n_nodes]
    float* out = (float*)d_out;

    int n_nodes = in_sizes[3];
    if (n_nodes > MAX_NODES) n_nodes = MAX_NODES;
    int n_edges = in_sizes[2] / 2;
    const int* src = eidx;
    const int* dst = eidx + n_edges;

    const int T = 256;

    k_zero <<<(MAX_NODES * NTYPES / 4 + T - 1) / T, T>>>(out);
    k_count<<<(n_edges + T - 1) / T, T>>>(src, dst, types, n_edges);
    k_prep <<<(n_nodes + T - 1) / T, T>>>(reps, types, n_nodes);

    dim3 grid((n_nodes + 255) / 256, NTYPES, D / RPB);   // non-working blocks exit early
    k_node <<<grid, 256>>>(rmaps, out);
}